// round 13
// baseline (speedup 1.0000x reference)
#include <cuda_runtime.h>

// All-pairs N-body gravity — SINGLE graph node with R5-class inner economics.
// R12 proved one-node works but lost IPT=2 (double LDS/pair) and used
// redundant per-warp staging. Fix: 256 thr = 32 j-slices x 8 i-groups, each
// thread runs 2 independent i-chains (R5's proven ILP + LDS amortization)
// over its 256-j slice; whole-block cooperative staging in 8 rounds; shared
// cross-slice reduction; one plain STG per output. No atomics, no zero pass,
// no second node (~3.3us/replay saved vs R11).

#define BLOCK   256
#define ITILE   16                 // i per CTA
#define NSLICE  32                 // j-slices
#define JSLICE  256                // j per slice (8192/32)
#define CHUNK   32                 // j per slice per staging round
#define CW      (CHUNK / 2)        // packed words per slice per round
#define NROUND  (JSLICE / CHUNK)   // 8
#define EPS2    0.0001f            // SOFTENING^2

typedef unsigned long long u64;

__device__ __forceinline__ u64 pack2(float lo, float hi) {
    u64 r;
    asm("mov.b64 %0, {%1, %2};" : "=l"(r)
        : "r"(__float_as_uint(lo)), "r"(__float_as_uint(hi)));
    return r;
}
__device__ __forceinline__ void unpack2(u64 v, float& lo, float& hi) {
    unsigned a, b;
    asm("mov.b64 {%0, %1}, %2;" : "=r"(a), "=r"(b) : "l"(v));
    lo = __uint_as_float(a);
    hi = __uint_as_float(b);
}
__device__ __forceinline__ u64 f2add(u64 a, u64 b) {
    u64 r; asm("add.rn.f32x2 %0, %1, %2;" : "=l"(r) : "l"(a), "l"(b)); return r;
}
__device__ __forceinline__ u64 f2mul(u64 a, u64 b) {
    u64 r; asm("mul.rn.f32x2 %0, %1, %2;" : "=l"(r) : "l"(a), "l"(b)); return r;
}
__device__ __forceinline__ u64 f2fma(u64 a, u64 b, u64 c) {
    u64 r; asm("fma.rn.f32x2 %0, %1, %2, %3;"
               : "=l"(r) : "l"(a), "l"(b), "l"(c)); return r;
}
__device__ __forceinline__ float rsq_mufu(float x) {
    float r; asm("rsqrt.approx.f32 %0, %1;" : "=f"(r) : "f"(x)); return r;
}

__global__ __launch_bounds__(BLOCK)
void nbody_forces_kernel(const float* __restrict__ pos,
                         const float* __restrict__ mass,
                         float* __restrict__ out) {
    // Packed SoA staging for all 32 slices' current chunk (16 KB).
    __shared__ u64 sx[NSLICE * CW], sy[NSLICE * CW],
                   sz[NSLICE * CW], sm[NSLICE * CW];
    // Cross-slice partials: [slice][dim][i_local], padded stride.
    __shared__ float red[NSLICE][3][ITILE + 1];

    const int tid   = threadIdx.x;
    const int slice = tid >> 3;        // 0..31
    const int ig    = tid & 7;         // i-group 0..7
    const int i0    = blockIdx.x * ITILE + ig;
    const int i1    = i0 + 8;

    const u64 nx0 = pack2(-pos[3 * i0 + 0], -pos[3 * i0 + 0]);
    const u64 ny0 = pack2(-pos[3 * i0 + 1], -pos[3 * i0 + 1]);
    const u64 nz0 = pack2(-pos[3 * i0 + 2], -pos[3 * i0 + 2]);
    const u64 nx1 = pack2(-pos[3 * i1 + 0], -pos[3 * i1 + 0]);
    const u64 ny1 = pack2(-pos[3 * i1 + 1], -pos[3 * i1 + 1]);
    const u64 nz1 = pack2(-pos[3 * i1 + 2], -pos[3 * i1 + 2]);
    const u64 eps22 = pack2(EPS2, EPS2);

    u64 ax0 = 0ull, ay0 = 0ull, az0 = 0ull;
    u64 ax1 = 0ull, ay1 = 0ull, az1 = 0ull;

    for (int r = 0; r < NROUND; ++r) {
        __syncthreads();
        // Cooperative staging: 32 j per slice for all slices (1024 j).
#pragma unroll
        for (int idx = tid; idx < NSLICE * CHUNK; idx += BLOCK) {
            const int s = idx >> 5;          // slice
            const int q = idx & 31;          // j within chunk
            const int j = s * JSLICE + r * CHUNK + q;
            ((float*)sx)[idx] = pos[3 * j + 0];
            ((float*)sy)[idx] = pos[3 * j + 1];
            ((float*)sz)[idx] = pos[3 * j + 2];
            ((float*)sm)[idx] = mass[j];
        }
        __syncthreads();

        const int base = slice * CW;
#pragma unroll
        for (int t = 0; t < CW; ++t) {
            const u64 px = sx[base + t];     // LDS.64 feeds 4 pairs (2i x 2j)
            const u64 py = sy[base + t];
            const u64 pz = sz[base + t];
            const u64 pm = sm[base + t];

            // chain 0
            u64 dx0 = f2add(px, nx0);
            u64 dy0 = f2add(py, ny0);
            u64 dz0 = f2add(pz, nz0);
            // chain 1 (independent)
            u64 dx1 = f2add(px, nx1);
            u64 dy1 = f2add(py, ny1);
            u64 dz1 = f2add(pz, nz1);

            u64 r20 = f2fma(dx0, dx0, f2fma(dy0, dy0, f2fma(dz0, dz0, eps22)));
            u64 r21 = f2fma(dx1, dx1, f2fma(dy1, dy1, f2fma(dz1, dz1, eps22)));

            float a, b;
            unpack2(r20, a, b);
            u64 inv0 = pack2(rsq_mufu(a), rsq_mufu(b));
            unpack2(r21, a, b);
            u64 inv1 = pack2(rsq_mufu(a), rsq_mufu(b));

            u64 s0 = f2mul(pm, f2mul(f2mul(inv0, inv0), inv0));
            u64 s1 = f2mul(pm, f2mul(f2mul(inv1, inv1), inv1));

            ax0 = f2fma(s0, dx0, ax0);
            ay0 = f2fma(s0, dy0, ay0);
            az0 = f2fma(s0, dz0, az0);
            ax1 = f2fma(s1, dx1, ax1);
            ay1 = f2fma(s1, dy1, ay1);
            az1 = f2fma(s1, dz1, az1);
        }
    }

    // Per-(slice, i) partials into shared.
    float l, h;
    unpack2(ax0, l, h); red[slice][0][ig]     = l + h;
    unpack2(ay0, l, h); red[slice][1][ig]     = l + h;
    unpack2(az0, l, h); red[slice][2][ig]     = l + h;
    unpack2(ax1, l, h); red[slice][0][ig + 8] = l + h;
    unpack2(ay1, l, h); red[slice][1][ig + 8] = l + h;
    unpack2(az1, l, h); red[slice][2][ig + 8] = l + h;
    __syncthreads();

    // Reduce 32 slice-partials; one plain STG per output element.
    if (tid < ITILE * 3) {
        const int ii  = tid & 15;
        const int dim = tid >> 4;            // 0..2
        float v = 0.0f;
#pragma unroll
        for (int s = 0; s < NSLICE; ++s) v += red[s][dim][ii];
        out[3 * (blockIdx.x * ITILE + ii) + dim] = v;
    }
}

extern "C" void kernel_launch(void* const* d_in, const int* in_sizes, int n_in,
                              void* d_out, int out_size) {
    const float* pos  = (const float*)d_in[0];   // [N,3] float32
    const float* mass = (const float*)d_in[1];   // [N]   float32
    float* out = (float*)d_out;                  // [N,3] float32

    const int n = in_sizes[0] / 3;               // 8192

    // One node: every out element written exactly once, no zeroing needed.
    nbody_forces_kernel<<<n / ITILE, BLOCK>>>(pos, mass, out);   // 512 CTAs
}